// round 2
// baseline (speedup 1.0000x reference)
#include <cuda_runtime.h>
#include <cuda_bf16.h>
#include <math.h>

// Problem constants
#define DM   2048          // d_model
#define NH   16            // heads
#define DH   128           // head dim
#define TS   2048          // seq len
#define BB   2             // batch
#define MROWS (BB*TS)      // 4096
#define BHN   (BB*NH)      // 32

// Scratch (static device allocations are the allowed mechanism)
__device__ float g_q[BHN * TS * DH];     // (B,H,T,Dh)
__device__ float g_k[BHN * TS * DH];
__device__ float g_v[BHN * TS * DH];
__device__ float g_att[MROWS * DM];      // (B,T,D) attention output

__device__ __forceinline__ int swz(int kk) { return ((kk >> 2) & 15) << 2; }

// ---------------------------------------------------------------------------
// Generic C = A(M x K) * W(N x K)^T + bias,  64x64 tile, BK=16, 256 threads,
// 4x4 per-thread register tile. SMEM stored k-major with XOR swizzle so the
// compute loop uses conflict-free float4 LDS.
// MODE 0: C[m*DM + n]   (plain row-major, used for output projection)
// MODE 1: C[((b*NH+h)*TS + t)*DH + d]  (scatter into (B,H,T,Dh) for attention)
// ---------------------------------------------------------------------------
template<int MODE>
__global__ void __launch_bounds__(256) gemm64(
    const float* __restrict__ A, const float* __restrict__ W,
    const float* __restrict__ bias, float* __restrict__ C, int K)
{
    __shared__ float As[16 * 64];
    __shared__ float Bs[16 * 64];

    const int tid = threadIdx.x;
    const int tx = tid & 15;
    const int ty = tid >> 4;
    const int row0 = blockIdx.y * 64;
    const int col0 = blockIdx.x * 64;

    const int m  = tid >> 2;   // 0..63 tile row (for loads)
    const int k4 = tid & 3;    // which float4 along k

    const float* Ap = A + (size_t)(row0 + m) * K + k4 * 4;
    const float* Wp = W + (size_t)(col0 + m) * K + k4 * 4;

    float acc[4][4];
#pragma unroll
    for (int i = 0; i < 4; i++)
#pragma unroll
        for (int j = 0; j < 4; j++) acc[i][j] = 0.f;

    for (int kt = 0; kt < K; kt += 16) {
        float4 av = *(const float4*)(Ap + kt);
        float4 wv = *(const float4*)(Wp + kt);
        const int kk = k4 * 4;
        As[(kk + 0) * 64 + (m ^ swz(kk + 0))] = av.x;
        As[(kk + 1) * 64 + (m ^ swz(kk + 1))] = av.y;
        As[(kk + 2) * 64 + (m ^ swz(kk + 2))] = av.z;
        As[(kk + 3) * 64 + (m ^ swz(kk + 3))] = av.w;
        Bs[(kk + 0) * 64 + (m ^ swz(kk + 0))] = wv.x;
        Bs[(kk + 1) * 64 + (m ^ swz(kk + 1))] = wv.y;
        Bs[(kk + 2) * 64 + (m ^ swz(kk + 2))] = wv.z;
        Bs[(kk + 3) * 64 + (m ^ swz(kk + 3))] = wv.w;
        __syncthreads();

#pragma unroll
        for (int k = 0; k < 16; k++) {
            float4 a = *(const float4*)&As[k * 64 + ((ty * 4) ^ swz(k))];
            float4 b = *(const float4*)&Bs[k * 64 + ((tx * 4) ^ swz(k))];
            float ar[4] = {a.x, a.y, a.z, a.w};
            float br[4] = {b.x, b.y, b.z, b.w};
#pragma unroll
            for (int i = 0; i < 4; i++)
#pragma unroll
                for (int j = 0; j < 4; j++)
                    acc[i][j] = fmaf(ar[i], br[j], acc[i][j]);
        }
        __syncthreads();
    }

#pragma unroll
    for (int i = 0; i < 4; i++) {
        const int mm = row0 + ty * 4 + i;
#pragma unroll
        for (int j = 0; j < 4; j++) {
            const int nn = col0 + tx * 4 + j;
            const float val = acc[i][j] + bias[nn];
            if (MODE == 0) {
                C[(size_t)mm * DM + nn] = val;
            } else {
                const int b = mm >> 11;      // /TS
                const int t = mm & (TS - 1);
                const int h = nn >> 7;       // /DH
                const int d = nn & (DH - 1);
                C[(((size_t)(b * NH + h)) * TS + t) * DH + d] = val;
            }
        }
    }
}

// ---------------------------------------------------------------------------
// In-place RoPE on q and k, layout (B,H,T,Dh). One thread per (bh, t, d<64).
// ---------------------------------------------------------------------------
__global__ void rope_kernel(float* __restrict__ q, float* __restrict__ k,
                            const float* __restrict__ sn, const float* __restrict__ cs)
{
    const int idx = blockIdx.x * blockDim.x + threadIdx.x;  // BHN*TS*64 total
    const int d  = idx & 63;
    const int t  = (idx >> 6) & (TS - 1);
    const int bh = idx >> 17;   // / (TS*64)
    const float s = sn[t * 64 + d];
    const float c = cs[t * 64 + d];
    const size_t base = ((size_t)bh * TS + t) * DH;

    float q1 = q[base + d], q2 = q[base + 64 + d];
    q[base + d]      = q1 * c - q2 * s;
    q[base + 64 + d] = q1 * s + q2 * c;

    float k1 = k[base + d], k2 = k[base + 64 + d];
    k[base + d]      = k1 * c - k2 * s;
    k[base + 64 + d] = k1 * s + k2 * c;
}

// ---------------------------------------------------------------------------
// Causal flash attention. Grid (T/64, B*H). 256 threads, per-thread: 4 query
// rows x (4 score cols | 8 output cols). Q/K SMEM k-major+swizzled for
// conflict-free float4 LDS; V natural; P round-trips through SMEM.
// Writes directly into (B,T,D) layout for the output projection.
// ---------------------------------------------------------------------------
__global__ void __launch_bounds__(256) flash_kernel(
    const float* __restrict__ q, const float* __restrict__ k,
    const float* __restrict__ v, float* __restrict__ att)
{
    extern __shared__ float sm[];
    float* Qs = sm;              // [128][64] k-major swizzled
    float* Ks = sm + 8192;       // [128][64] k-major swizzled
    float* Vs = sm + 16384;      // [64][128] natural
    float* Ps = sm + 24576;      // [64][65]

    const int tid = threadIdx.x;
    const int tx = tid & 15;
    const int ty = tid >> 4;
    const int qt = blockIdx.x;
    const int bh = blockIdx.y;

    const float* qbase = q + (((size_t)bh * TS) + qt * 64) * DH;
    const float* kbase = k + (size_t)bh * TS * DH;
    const float* vbase = v + (size_t)bh * TS * DH;

    const float scale = 0.08838834764831845f;   // 1/sqrt(128)

    // Load Q tile (transposed + swizzled), pre-scaled
#pragma unroll
    for (int it = 0; it < 8; it++) {
        const int f = tid + it * 256;
        const int mm = f >> 5;
        const int c4 = f & 31;
        float4 vq = *(const float4*)(qbase + (size_t)mm * DH + c4 * 4);
        const int kk = c4 * 4;
        Qs[(kk + 0) * 64 + (mm ^ swz(kk + 0))] = vq.x * scale;
        Qs[(kk + 1) * 64 + (mm ^ swz(kk + 1))] = vq.y * scale;
        Qs[(kk + 2) * 64 + (mm ^ swz(kk + 2))] = vq.z * scale;
        Qs[(kk + 3) * 64 + (mm ^ swz(kk + 3))] = vq.w * scale;
    }

    float mi[4], li[4], Oa[4][8];
#pragma unroll
    for (int i = 0; i < 4; i++) {
        mi[i] = -INFINITY; li[i] = 0.f;
#pragma unroll
        for (int c = 0; c < 8; c++) Oa[i][c] = 0.f;
    }

    for (int j = 0; j <= qt; j++) {
        __syncthreads();   // protects Ks/Vs/Ps reuse (and Q visibility on j=0)

        // Load K tile (transposed+swizzled) and V tile (natural)
#pragma unroll
        for (int it = 0; it < 8; it++) {
            const int f = tid + it * 256;
            const int mm = f >> 5;
            const int c4 = f & 31;
            const size_t roff = ((size_t)(j * 64 + mm)) * DH + c4 * 4;
            float4 vk = *(const float4*)(kbase + roff);
            const int kk = c4 * 4;
            Ks[(kk + 0) * 64 + (mm ^ swz(kk + 0))] = vk.x;
            Ks[(kk + 1) * 64 + (mm ^ swz(kk + 1))] = vk.y;
            Ks[(kk + 2) * 64 + (mm ^ swz(kk + 2))] = vk.z;
            Ks[(kk + 3) * 64 + (mm ^ swz(kk + 3))] = vk.w;
            float4 vv = *(const float4*)(vbase + roff);
            *(float4*)(Vs + mm * 128 + c4 * 4) = vv;
        }
        __syncthreads();

        // S = Q K^T (per-thread 4x4 over rows ty*4.., cols tx*4..)
        float S[4][4];
#pragma unroll
        for (int i = 0; i < 4; i++)
#pragma unroll
            for (int jj = 0; jj < 4; jj++) S[i][jj] = 0.f;

#pragma unroll 16
        for (int kk = 0; kk < 128; kk++) {
            float4 a = *(const float4*)&Qs[kk * 64 + ((ty * 4) ^ swz(kk))];
            float4 b = *(const float4*)&Ks[kk * 64 + ((tx * 4) ^ swz(kk))];
            float ar[4] = {a.x, a.y, a.z, a.w};
            float br[4] = {b.x, b.y, b.z, b.w};
#pragma unroll
            for (int i = 0; i < 4; i++)
#pragma unroll
                for (int jj = 0; jj < 4; jj++)
                    S[i][jj] = fmaf(ar[i], br[jj], S[i][jj]);
        }

        // Causal mask on the diagonal tile
        if (j == qt) {
#pragma unroll
            for (int i = 0; i < 4; i++)
#pragma unroll
                for (int jj = 0; jj < 4; jj++)
                    if (tx * 4 + jj > ty * 4 + i) S[i][jj] = -INFINITY;
        }

        // Online softmax update per row
#pragma unroll
        for (int i = 0; i < 4; i++) {
            float rmax = fmaxf(fmaxf(S[i][0], S[i][1]), fmaxf(S[i][2], S[i][3]));
#pragma unroll
            for (int off = 8; off > 0; off >>= 1)
                rmax = fmaxf(rmax, __shfl_xor_sync(0xffffffffu, rmax, off, 16));
            const float mnew = fmaxf(mi[i], rmax);
            float p[4], rsum = 0.f;
#pragma unroll
            for (int jj = 0; jj < 4; jj++) {
                p[jj] = __expf(S[i][jj] - mnew);
                rsum += p[jj];
            }
#pragma unroll
            for (int off = 8; off > 0; off >>= 1)
                rsum += __shfl_xor_sync(0xffffffffu, rsum, off, 16);
            const float alpha = __expf(mi[i] - mnew);
            li[i] = li[i] * alpha + rsum;
            mi[i] = mnew;
#pragma unroll
            for (int c = 0; c < 8; c++) Oa[i][c] *= alpha;
            float* pr = Ps + (ty * 4 + i) * 65 + tx * 4;
            pr[0] = p[0]; pr[1] = p[1]; pr[2] = p[2]; pr[3] = p[3];
        }
        __syncthreads();

        // O += P V : per-thread cols tx*4..tx*4+3 and 64+tx*4..64+tx*4+3
#pragma unroll 4
        for (int n = 0; n < 64; n++) {
            float pr[4];
#pragma unroll
            for (int i = 0; i < 4; i++) pr[i] = Ps[(ty * 4 + i) * 65 + n];
            float4 v0 = *(const float4*)(Vs + n * 128 + tx * 4);
            float4 v1 = *(const float4*)(Vs + n * 128 + 64 + tx * 4);
            float vr[8] = {v0.x, v0.y, v0.z, v0.w, v1.x, v1.y, v1.z, v1.w};
#pragma unroll
            for (int i = 0; i < 4; i++)
#pragma unroll
                for (int c = 0; c < 8; c++)
                    Oa[i][c] = fmaf(pr[i], vr[c], Oa[i][c]);
        }
    }

    // Epilogue: normalize, scatter into (B,T,D)
    const int b = bh >> 4;
    const int h = bh & 15;
#pragma unroll
    for (int i = 0; i < 4; i++) {
        const float inv = 1.f / li[i];
        const int t = qt * 64 + ty * 4 + i;
        float* dst = att + ((size_t)(b * TS + t)) * DM + h * DH;
        float4 o0 = make_float4(Oa[i][0] * inv, Oa[i][1] * inv, Oa[i][2] * inv, Oa[i][3] * inv);
        float4 o1 = make_float4(Oa[i][4] * inv, Oa[i][5] * inv, Oa[i][6] * inv, Oa[i][7] * inv);
        *(float4*)(dst + tx * 4)      = o0;
        *(float4*)(dst + 64 + tx * 4) = o1;
    }
}

// ---------------------------------------------------------------------------
extern "C" void kernel_launch(void* const* d_in, const int* in_sizes, int n_in,
                              void* d_out, int out_size)
{
    (void)in_sizes; (void)n_in; (void)out_size;
    const float* x  = (const float*)d_in[0];
    const float* Wq = (const float*)d_in[1];
    const float* bq = (const float*)d_in[2];
    const float* Wk = (const float*)d_in[3];
    const float* bk = (const float*)d_in[4];
    const float* Wv = (const float*)d_in[5];
    const float* bv = (const float*)d_in[6];
    const float* Wo = (const float*)d_in[7];
    const float* bo = (const float*)d_in[8];
    const float* sn = (const float*)d_in[9];
    const float* cs = (const float*)d_in[10];
    float* out = (float*)d_out;

    float *q, *k, *v, *att;
    cudaGetSymbolAddress((void**)&q,   g_q);
    cudaGetSymbolAddress((void**)&k,   g_k);
    cudaGetSymbolAddress((void**)&v,   g_v);
    cudaGetSymbolAddress((void**)&att, g_att);

    const dim3 ggrid(DM / 64, MROWS / 64);   // (32, 64)

    // QKV projections (scatter into (B,H,T,Dh))
    gemm64<1><<<ggrid, 256>>>(x, Wq, bq, q, DM);
    gemm64<1><<<ggrid, 256>>>(x, Wk, bk, k, DM);
    gemm64<1><<<ggrid, 256>>>(x, Wv, bv, v, DM);

    // RoPE in place on q, k
    rope_kernel<<<(BHN * TS * 64) / 256, 256>>>(q, k, sn, cs);

    // Flash attention
    static int smem_set = 0;
    const int flash_smem = (8192 * 3 + 64 * 65) * (int)sizeof(float);  // 114944 B
    if (!smem_set) {
        cudaFuncSetAttribute(flash_kernel,
                             cudaFuncAttributeMaxDynamicSharedMemorySize, flash_smem);
        smem_set = 1;
    }
    flash_kernel<<<dim3(TS / 64, BHN), 256, flash_smem>>>(q, k, v, att);

    // Output projection
    gemm64<0><<<ggrid, 256>>>(att, Wo, bo, out, DM);
}

// round 4
// speedup vs baseline: 1.9798x; 1.9798x over previous
#include <cuda_runtime.h>
#include <cuda_bf16.h>
#include <math.h>
#include <stdint.h>

// Problem constants
#define DM   2048
#define NH   16
#define DH   128
#define SEQ  2048
#define BB   2
#define MROWS (BB*SEQ)     // 4096
#define BHN   (BB*NH)      // 32

// ---------------- scratch (static device arrays per harness rules) ----------
__device__ float g_q[BHN * SEQ * DH];
__device__ float g_k[BHN * SEQ * DH];
__device__ float g_v[BHN * SEQ * DH];
__device__ __nv_bfloat16 g_xh[MROWS * DM], g_xl[MROWS * DM];
__device__ __nv_bfloat16 g_wh[4 * DM * DM], g_wl[4 * DM * DM];   // q,k,v,o
__device__ __nv_bfloat16 g_ah[MROWS * DM], g_al[MROWS * DM];     // att split

// ---------------- helpers ---------------------------------------------------
__device__ __forceinline__ uint32_t smem_u32(const void* p) {
    uint32_t a;
    asm("{ .reg .u64 t; cvta.to.shared.u64 t, %1; cvt.u32.u64 %0, t; }"
        : "=r"(a) : "l"(p));
    return a;
}

__device__ __forceinline__ void cpa16(uint32_t s, const void* g) {
    asm volatile("cp.async.cg.shared.global [%0], [%1], 16;" :: "r"(s), "l"(g));
}
__device__ __forceinline__ void cpa_commit() {
    asm volatile("cp.async.commit_group;" ::: "memory");
}
template<int N>
__device__ __forceinline__ void cpa_wait() {
    asm volatile("cp.async.wait_group %0;" :: "n"(N) : "memory");
}

__device__ __forceinline__ void ldsm4(uint32_t* r, uint32_t addr) {
    asm volatile("ldmatrix.sync.aligned.m8n8.x4.shared.b16 {%0,%1,%2,%3}, [%4];"
                 : "=r"(r[0]), "=r"(r[1]), "=r"(r[2]), "=r"(r[3]) : "r"(addr));
}

__device__ __forceinline__ void mma16816(float* c, const uint32_t* a, const uint32_t* b) {
    asm volatile("mma.sync.aligned.m16n8k16.row.col.f32.bf16.bf16.f32 "
                 "{%0,%1,%2,%3}, {%4,%5,%6,%7}, {%8,%9}, {%0,%1,%2,%3};"
                 : "+f"(c[0]), "+f"(c[1]), "+f"(c[2]), "+f"(c[3])
                 : "r"(a[0]), "r"(a[1]), "r"(a[2]), "r"(a[3]),
                   "r"(b[0]), "r"(b[1]));
}

// ---------------------------------------------------------------------------
// fp32 -> (hi, lo) bf16 split, vectorized x4
// ---------------------------------------------------------------------------
__global__ void split_kernel(const float* __restrict__ src,
                             __nv_bfloat16* __restrict__ hi,
                             __nv_bfloat16* __restrict__ lo, int n4)
{
    int i = blockIdx.x * blockDim.x + threadIdx.x;
    if (i >= n4) return;
    float4 v = ((const float4*)src)[i];
    __nv_bfloat16 h0 = __float2bfloat16(v.x), h1 = __float2bfloat16(v.y);
    __nv_bfloat16 h2 = __float2bfloat16(v.z), h3 = __float2bfloat16(v.w);
    __nv_bfloat16 l0 = __float2bfloat16(v.x - __bfloat162float(h0));
    __nv_bfloat16 l1 = __float2bfloat16(v.y - __bfloat162float(h1));
    __nv_bfloat16 l2 = __float2bfloat16(v.z - __bfloat162float(h2));
    __nv_bfloat16 l3 = __float2bfloat16(v.w - __bfloat162float(h3));
    ((__nv_bfloat162*)hi)[2 * i]     = __halves2bfloat162(h0, h1);
    ((__nv_bfloat162*)hi)[2 * i + 1] = __halves2bfloat162(h2, h3);
    ((__nv_bfloat162*)lo)[2 * i]     = __halves2bfloat162(l0, l1);
    ((__nv_bfloat162*)lo)[2 * i + 1] = __halves2bfloat162(l2, l3);
}

// ---------------------------------------------------------------------------
// mma.sync split-bf16 GEMM: C(128x128 per CTA) = A(MxK) W(NxK)^T + bias
// D += Ah*Wh + Ah*Wl + Al*Wh  (fp32 accumulators in registers)
// BK=32, 2-stage cp.async pipeline, smem row stride 40 bf16 (conflict-free
// ldmatrix). 8 warps in 2x4 grid; each warp 64x32 via 4x4 m16n8k16 frags.
// MODE 0: C row-major [M][DM]; MODE 1: scatter to (B,H,T,Dh)
// ---------------------------------------------------------------------------
#define BK    32
#define TSTR  40                    // smem row stride (bf16 elements)
#define TILE_B (128 * TSTR * 2)     // 10240 B per tile
#define BUF_B  (4 * TILE_B)         // 40960 B per stage (Ah, Al, Wh, Wl)
#define GM_SMEM (2 * BUF_B)         // 81920 B

template<int MODE>
__global__ void __launch_bounds__(256) gemm_mma(
    const __nv_bfloat16* __restrict__ Ah, const __nv_bfloat16* __restrict__ Al,
    const __nv_bfloat16* __restrict__ Wh, const __nv_bfloat16* __restrict__ Wl,
    const float* __restrict__ bias, float* __restrict__ C)
{
    extern __shared__ __align__(128) char smem[];
    const uint32_t sbase = smem_u32(smem);
    const int tid  = threadIdx.x;
    const int wid  = tid >> 5;
    const int lane = tid & 31;
    const int row0 = blockIdx.y * 128;
    const int col0 = blockIdx.x * 128;
    const int wm = (wid >> 2) * 64;     // warp m offset in tile
    const int wn = (wid & 3) * 32;      // warp n offset in tile

    const __nv_bfloat16* gsrc[4] = {Ah, Al, Wh, Wl};

    // ---- async load of one K-slab into stage buffer ----
    auto issue = [&](int kt, int buf) {
#pragma unroll
        for (int t = 0; t < 4; t++) {
            const __nv_bfloat16* g = gsrc[t];
            const int rb = (t < 2) ? row0 : col0;
            const uint32_t sb = sbase + buf * BUF_B + t * TILE_B;
#pragma unroll
            for (int i = 0; i < 2; i++) {
                const int ch = tid + i * 256;       // 512 chunks of 16B
                const int r = ch >> 2, c = ch & 3;
                cpa16(sb + r * (TSTR * 2) + c * 16,
                      g + (size_t)(rb + r) * DM + kt * BK + c * 8);
            }
        }
        cpa_commit();
    };

    float acc[4][4][4];
#pragma unroll
    for (int i = 0; i < 4; i++)
#pragma unroll
        for (int j = 0; j < 4; j++)
#pragma unroll
            for (int c = 0; c < 4; c++) acc[i][j][c] = 0.f;

    // ldmatrix lane addressing (precompute offsets within a tile)
    const int mi = lane >> 3;           // which 8x8 matrix
    const int l7 = lane & 7;
    // A: matrices [m0k0, m8k0, m0k8, m8k8]
    const int a_r  = ((mi & 1) << 3) + l7;
    const int a_kb = (mi >> 1) << 3;
    // B(W): group g covers ntiles 2g,2g+1: [nt0 k0, nt0 k8, nt1 k0, nt1 k8]
    const int b_nt = mi >> 1;
    const int b_kb = (mi & 1) << 3;

    const int NKT = DM / BK;            // 64
    issue(0, 0);

    for (int kt = 0; kt < NKT; kt++) {
        const int buf = kt & 1;
        if (kt + 1 < NKT) { issue(kt + 1, buf ^ 1); cpa_wait<1>(); }
        else              { cpa_wait<0>(); }
        __syncthreads();

        const uint32_t sb = sbase + buf * BUF_B;
#pragma unroll
        for (int kh = 0; kh < 2; kh++) {            // two k16 steps per slab
            uint32_t afh[4][4], afl[4][4];
#pragma unroll
            for (int mt = 0; mt < 4; mt++) {
                const uint32_t ad = sb +
                    (wm + mt * 16 + a_r) * (TSTR * 2) + (kh * 16 + a_kb) * 2;
                ldsm4(afh[mt], ad);                 // Ah tile at offset 0
                ldsm4(afl[mt], ad + TILE_B);        // Al tile
            }
            uint32_t bfh[8], bfl[8];
#pragma unroll
            for (int g = 0; g < 2; g++) {
                const uint32_t bd = sb + 2 * TILE_B +
                    (wn + (2 * g + b_nt) * 8 + l7) * (TSTR * 2) +
                    (kh * 16 + b_kb) * 2;
                ldsm4(&bfh[g * 4], bd);             // Wh tile
                ldsm4(&bfl[g * 4], bd + TILE_B);    // Wl tile
            }
#pragma unroll
            for (int mt = 0; mt < 4; mt++)
#pragma unroll
                for (int nt = 0; nt < 4; nt++) {
                    float* c = acc[mt][nt];
                    mma16816(c, afh[mt], &bfh[nt * 2]);
                    mma16816(c, afh[mt], &bfl[nt * 2]);
                    mma16816(c, afl[mt], &bfh[nt * 2]);
                }
        }
        __syncthreads();
    }

    // ---- epilogue: registers -> global (+bias) ----
#pragma unroll
    for (int mt = 0; mt < 4; mt++) {
#pragma unroll
        for (int nt = 0; nt < 4; nt++) {
            const int cc = col0 + wn + nt * 8 + (lane & 3) * 2;
            const float b0 = bias[cc], b1 = bias[cc + 1];
#pragma unroll
            for (int half = 0; half < 2; half++) {
                const int rr = row0 + wm + mt * 16 + (lane >> 2) + half * 8;
                float2 v;
                v.x = acc[mt][nt][half * 2 + 0] + b0;
                v.y = acc[mt][nt][half * 2 + 1] + b1;
                if (MODE == 0) {
                    *(float2*)(C + (size_t)rr * DM + cc) = v;
                } else {
                    const int b  = rr >> 11;
                    const int tt = rr & (SEQ - 1);
                    const int h  = cc >> 7;
                    const int d0 = cc & (DH - 1);
                    *(float2*)(C + (((size_t)(b * NH + h)) * SEQ + tt) * DH + d0) = v;
                }
            }
        }
    }
}

// ---------------------------------------------------------------------------
// In-place RoPE on q and k, layout (B,H,T,Dh).
// ---------------------------------------------------------------------------
__global__ void rope_kernel(float* __restrict__ q, float* __restrict__ k,
                            const float* __restrict__ sn, const float* __restrict__ cs)
{
    const int idx = blockIdx.x * blockDim.x + threadIdx.x;
    const int d  = idx & 63;
    const int t  = (idx >> 6) & (SEQ - 1);
    const int bh = idx >> 17;
    const float s = sn[t * 64 + d];
    const float c = cs[t * 64 + d];
    const size_t base = ((size_t)bh * SEQ + t) * DH;

    float q1 = q[base + d], q2 = q[base + 64 + d];
    q[base + d]      = q1 * c - q2 * s;
    q[base + 64 + d] = q1 * s + q2 * c;

    float k1 = k[base + d], k2 = k[base + 64 + d];
    k[base + d]      = k1 * c - k2 * s;
    k[base + 64 + d] = k1 * s + k2 * c;
}

// ---------------------------------------------------------------------------
// Causal flash attention (fp32 FMA). Epilogue emits split-bf16 att directly.
// ---------------------------------------------------------------------------
__device__ __forceinline__ int swz(int kk) { return ((kk >> 2) & 15) << 2; }

__global__ void __launch_bounds__(256) flash_kernel(
    const float* __restrict__ q, const float* __restrict__ k,
    const float* __restrict__ v,
    __nv_bfloat16* __restrict__ att_hi, __nv_bfloat16* __restrict__ att_lo)
{
    extern __shared__ float sm[];
    float* Qs = sm;              // [128][64] k-major swizzled
    float* Ks = sm + 8192;
    float* Vs = sm + 16384;      // [64][128]
    float* Ps = sm + 24576;      // [64][65]

    const int tid = threadIdx.x;
    const int tx = tid & 15;
    const int ty = tid >> 4;
    const int qt = blockIdx.x;
    const int bh = blockIdx.y;

    const float* qbase = q + (((size_t)bh * SEQ) + qt * 64) * DH;
    const float* kbase = k + (size_t)bh * SEQ * DH;
    const float* vbase = v + (size_t)bh * SEQ * DH;

    const float scale = 0.08838834764831845f;

#pragma unroll
    for (int it = 0; it < 8; it++) {
        const int f = tid + it * 256;
        const int mm = f >> 5;
        const int c4 = f & 31;
        float4 vq = *(const float4*)(qbase + (size_t)mm * DH + c4 * 4);
        const int kk = c4 * 4;
        Qs[(kk + 0) * 64 + (mm ^ swz(kk + 0))] = vq.x * scale;
        Qs[(kk + 1) * 64 + (mm ^ swz(kk + 1))] = vq.y * scale;
        Qs[(kk + 2) * 64 + (mm ^ swz(kk + 2))] = vq.z * scale;
        Qs[(kk + 3) * 64 + (mm ^ swz(kk + 3))] = vq.w * scale;
    }

    float mi[4], li[4], Oa[4][8];
#pragma unroll
    for (int i = 0; i < 4; i++) {
        mi[i] = -INFINITY; li[i] = 0.f;
#pragma unroll
        for (int c = 0; c < 8; c++) Oa[i][c] = 0.f;
    }

    for (int j = 0; j <= qt; j++) {
        __syncthreads();
#pragma unroll
        for (int it = 0; it < 8; it++) {
            const int f = tid + it * 256;
            const int mm = f >> 5;
            const int c4 = f & 31;
            const size_t roff = ((size_t)(j * 64 + mm)) * DH + c4 * 4;
            float4 vk = *(const float4*)(kbase + roff);
            const int kk = c4 * 4;
            Ks[(kk + 0) * 64 + (mm ^ swz(kk + 0))] = vk.x;
            Ks[(kk + 1) * 64 + (mm ^ swz(kk + 1))] = vk.y;
            Ks[(kk + 2) * 64 + (mm ^ swz(kk + 2))] = vk.z;
            Ks[(kk + 3) * 64 + (mm ^ swz(kk + 3))] = vk.w;
            float4 vv = *(const float4*)(vbase + roff);
            *(float4*)(Vs + mm * 128 + c4 * 4) = vv;
        }
        __syncthreads();

        float S[4][4];
#pragma unroll
        for (int i = 0; i < 4; i++)
#pragma unroll
            for (int jj = 0; jj < 4; jj++) S[i][jj] = 0.f;

#pragma unroll 16
        for (int kk = 0; kk < 128; kk++) {
            float4 a = *(const float4*)&Qs[kk * 64 + ((ty * 4) ^ swz(kk))];
            float4 b = *(const float4*)&Ks[kk * 64 + ((tx * 4) ^ swz(kk))];
            float ar[4] = {a.x, a.y, a.z, a.w};
            float br[4] = {b.x, b.y, b.z, b.w};
#pragma unroll
            for (int i = 0; i < 4; i++)
#pragma unroll
                for (int jj = 0; jj < 4; jj++)
                    S[i][jj] = fmaf(ar[i], br[jj], S[i][jj]);
        }

        if (j == qt) {
#pragma unroll
            for (int i = 0; i < 4; i++)
#pragma unroll
                for (int jj = 0; jj < 4; jj++)
                    if (tx * 4 + jj > ty * 4 + i) S[i][jj] = -INFINITY;
        }

#pragma unroll
        for (int i = 0; i < 4; i++) {
            float rmax = fmaxf(fmaxf(S[i][0], S[i][1]), fmaxf(S[i][2], S[i][3]));
#pragma unroll
            for (int off = 8; off > 0; off >>= 1)
                rmax = fmaxf(rmax, __shfl_xor_sync(0xffffffffu, rmax, off, 16));
            const float mnew = fmaxf(mi[i], rmax);
            float p[4], rsum = 0.f;
#pragma unroll
            for (int jj = 0; jj < 4; jj++) {
                p[jj] = __expf(S[i][jj] - mnew);
                rsum += p[jj];
            }
#pragma unroll
            for (int off = 8; off > 0; off >>= 1)
                rsum += __shfl_xor_sync(0xffffffffu, rsum, off, 16);
            const float alpha = __expf(mi[i] - mnew);
            li[i] = li[i] * alpha + rsum;
            mi[i] = mnew;
#pragma unroll
            for (int c = 0; c < 8; c++) Oa[i][c] *= alpha;
            float* pr = Ps + (ty * 4 + i) * 65 + tx * 4;
            pr[0] = p[0]; pr[1] = p[1]; pr[2] = p[2]; pr[3] = p[3];
        }
        __syncthreads();

#pragma unroll 4
        for (int n = 0; n < 64; n++) {
            float pr[4];
#pragma unroll
            for (int i = 0; i < 4; i++) pr[i] = Ps[(ty * 4 + i) * 65 + n];
            float4 v0 = *(const float4*)(Vs + n * 128 + tx * 4);
            float4 v1 = *(const float4*)(Vs + n * 128 + 64 + tx * 4);
            float vr[8] = {v0.x, v0.y, v0.z, v0.w, v1.x, v1.y, v1.z, v1.w};
#pragma unroll
            for (int i = 0; i < 4; i++)
#pragma unroll
                for (int c = 0; c < 8; c++)
                    Oa[i][c] = fmaf(pr[i], vr[c], Oa[i][c]);
        }
    }

    // Epilogue: normalize, split to bf16 hi/lo, scatter into (B,T,D)
    const int b = bh >> 4;
    const int h = bh & 15;
#pragma unroll
    for (int i = 0; i < 4; i++) {
        const float inv = 1.f / li[i];
        const int t = qt * 64 + ty * 4 + i;
        const size_t rowoff = ((size_t)(b * SEQ + t)) * DM + h * DH;
#pragma unroll
        for (int half = 0; half < 2; half++) {
            const size_t base = rowoff + half * 64 + tx * 4;
            float o0 = Oa[i][half * 4 + 0] * inv;
            float o1 = Oa[i][half * 4 + 1] * inv;
            float o2 = Oa[i][half * 4 + 2] * inv;
            float o3 = Oa[i][half * 4 + 3] * inv;
            __nv_bfloat16 h0 = __float2bfloat16(o0), h1 = __float2bfloat16(o1);
            __nv_bfloat16 h2 = __float2bfloat16(o2), h3 = __float2bfloat16(o3);
            __nv_bfloat16 l0 = __float2bfloat16(o0 - __bfloat162float(h0));
            __nv_bfloat16 l1 = __float2bfloat16(o1 - __bfloat162float(h1));
            __nv_bfloat16 l2 = __float2bfloat16(o2 - __bfloat162float(h2));
            __nv_bfloat16 l3 = __float2bfloat16(o3 - __bfloat162float(h3));
            *(__nv_bfloat162*)(att_hi + base)     = __halves2bfloat162(h0, h1);
            *(__nv_bfloat162*)(att_hi + base + 2) = __halves2bfloat162(h2, h3);
            *(__nv_bfloat162*)(att_lo + base)     = __halves2bfloat162(l0, l1);
            *(__nv_bfloat162*)(att_lo + base + 2) = __halves2bfloat162(l2, l3);
        }
    }
}

// ---------------------------------------------------------------------------
extern "C" void kernel_launch(void* const* d_in, const int* in_sizes, int n_in,
                              void* d_out, int out_size)
{
    (void)in_sizes; (void)n_in; (void)out_size;
    const float* x  = (const float*)d_in[0];
    const float* Wq = (const float*)d_in[1];
    const float* bq = (const float*)d_in[2];
    const float* Wk = (const float*)d_in[3];
    const float* bk = (const float*)d_in[4];
    const float* Wv = (const float*)d_in[5];
    const float* bv = (const float*)d_in[6];
    const float* Wo = (const float*)d_in[7];
    const float* bo = (const float*)d_in[8];
    const float* sn = (const float*)d_in[9];
    const float* cs = (const float*)d_in[10];
    float* out = (float*)d_out;

    float *q, *k, *v;
    __nv_bfloat16 *xh, *xl, *wh, *wl, *ah, *al;
    cudaGetSymbolAddress((void**)&q,  g_q);
    cudaGetSymbolAddress((void**)&k,  g_k);
    cudaGetSymbolAddress((void**)&v,  g_v);
    cudaGetSymbolAddress((void**)&xh, g_xh);
    cudaGetSymbolAddress((void**)&xl, g_xl);
    cudaGetSymbolAddress((void**)&wh, g_wh);
    cudaGetSymbolAddress((void**)&wl, g_wl);
    cudaGetSymbolAddress((void**)&ah, g_ah);
    cudaGetSymbolAddress((void**)&al, g_al);

    cudaFuncSetAttribute(gemm_mma<0>, cudaFuncAttributeMaxDynamicSharedMemorySize, GM_SMEM);
    cudaFuncSetAttribute(gemm_mma<1>, cudaFuncAttributeMaxDynamicSharedMemorySize, GM_SMEM);
    const int flash_smem = (8192 * 3 + 64 * 65) * (int)sizeof(float);
    cudaFuncSetAttribute(flash_kernel, cudaFuncAttributeMaxDynamicSharedMemorySize, flash_smem);

    // split conversions
    split_kernel<<<(MROWS * DM / 4) / 256, 256>>>(x, xh, xl, MROWS * DM / 4);
    const int wn4 = DM * DM / 4;
    split_kernel<<<wn4 / 256, 256>>>(Wq, wh + 0 * DM * DM, wl + 0 * DM * DM, wn4);
    split_kernel<<<wn4 / 256, 256>>>(Wk, wh + 1 * DM * DM, wl + 1 * DM * DM, wn4);
    split_kernel<<<wn4 / 256, 256>>>(Wv, wh + 2 * DM * DM, wl + 2 * DM * DM, wn4);
    split_kernel<<<wn4 / 256, 256>>>(Wo, wh + 3 * DM * DM, wl + 3 * DM * DM, wn4);

    // QKV projections on tensor cores (scatter into (B,H,T,Dh))
    const dim3 ggrid(DM / 128, MROWS / 128);   // (16, 32)
    gemm_mma<1><<<ggrid, 256, GM_SMEM>>>(xh, xl, wh + 0 * DM * DM, wl + 0 * DM * DM, bq, q);
    gemm_mma<1><<<ggrid, 256, GM_SMEM>>>(xh, xl, wh + 1 * DM * DM, wl + 1 * DM * DM, bk, k);
    gemm_mma<1><<<ggrid, 256, GM_SMEM>>>(xh, xl, wh + 2 * DM * DM, wl + 2 * DM * DM, bv, v);

    // RoPE
    rope_kernel<<<(BHN * SEQ * 64) / 256, 256>>>(q, k, sn, cs);

    // Flash attention (emits split-bf16 att)
    flash_kernel<<<dim3(SEQ / 64, BHN), 256, flash_smem>>>(q, k, v, ah, al);

    // Output projection on tensor cores
    gemm_mma<0><<<ggrid, 256, GM_SMEM>>>(ah, al, wh + 3 * DM * DM, wl + 3 * DM * DM, bo, out);
}

// round 5
// speedup vs baseline: 2.9939x; 1.5122x over previous
#include <cuda_runtime.h>
#include <cuda_bf16.h>
#include <math.h>
#include <stdint.h>

// Problem constants
#define DM   2048
#define NH   16
#define DH   128
#define SEQ  2048
#define BB   2
#define MROWS (BB*SEQ)     // 4096
#define BHN   (BB*NH)      // 32

// ---------------- scratch (static device arrays per harness rules) ----------
__device__ float g_q[BHN * SEQ * DH];
__device__ float g_k[BHN * SEQ * DH];
__device__ float g_v[BHN * SEQ * DH];
__device__ __nv_bfloat16 g_xh[MROWS * DM], g_xl[MROWS * DM];
__device__ __nv_bfloat16 g_wh[4 * DM * DM], g_wl[4 * DM * DM];   // q,k,v,o
__device__ __nv_bfloat16 g_ah[MROWS * DM], g_al[MROWS * DM];     // att split
// split q/k/v for tensor-core flash (q pre-scaled, rope applied)
__device__ __nv_bfloat16 g_qh[BHN * SEQ * DH], g_ql[BHN * SEQ * DH];
__device__ __nv_bfloat16 g_kh[BHN * SEQ * DH], g_kl[BHN * SEQ * DH];
__device__ __nv_bfloat16 g_vh[BHN * SEQ * DH], g_vl[BHN * SEQ * DH];

// ---------------- helpers ---------------------------------------------------
__device__ __forceinline__ uint32_t smem_u32(const void* p) {
    uint32_t a;
    asm("{ .reg .u64 t; cvta.to.shared.u64 t, %1; cvt.u32.u64 %0, t; }"
        : "=r"(a) : "l"(p));
    return a;
}
__device__ __forceinline__ void cpa16(uint32_t s, const void* g) {
    asm volatile("cp.async.cg.shared.global [%0], [%1], 16;" :: "r"(s), "l"(g));
}
__device__ __forceinline__ void cpa_commit() {
    asm volatile("cp.async.commit_group;" ::: "memory");
}
template<int N>
__device__ __forceinline__ void cpa_wait() {
    asm volatile("cp.async.wait_group %0;" :: "n"(N) : "memory");
}
__device__ __forceinline__ void ldsm4(uint32_t* r, uint32_t addr) {
    asm volatile("ldmatrix.sync.aligned.m8n8.x4.shared.b16 {%0,%1,%2,%3}, [%4];"
                 : "=r"(r[0]), "=r"(r[1]), "=r"(r[2]), "=r"(r[3]) : "r"(addr));
}
__device__ __forceinline__ void ldsm4t(uint32_t* r, uint32_t addr) {
    asm volatile("ldmatrix.sync.aligned.m8n8.x4.trans.shared.b16 {%0,%1,%2,%3}, [%4];"
                 : "=r"(r[0]), "=r"(r[1]), "=r"(r[2]), "=r"(r[3]) : "r"(addr));
}
__device__ __forceinline__ void mma16816(float* c, const uint32_t* a, const uint32_t* b) {
    asm volatile("mma.sync.aligned.m16n8k16.row.col.f32.bf16.bf16.f32 "
                 "{%0,%1,%2,%3}, {%4,%5,%6,%7}, {%8,%9}, {%0,%1,%2,%3};"
                 : "+f"(c[0]), "+f"(c[1]), "+f"(c[2]), "+f"(c[3])
                 : "r"(a[0]), "r"(a[1]), "r"(a[2]), "r"(a[3]),
                   "r"(b[0]), "r"(b[1]));
}
// pack two fp32 as bf16x2: low half = a (even col), high = b (odd col)
__device__ __forceinline__ uint32_t pack_hi_trunc(float a, float b) {
    return __byte_perm(__float_as_uint(a), __float_as_uint(b), 0x7632);
}
__device__ __forceinline__ uint32_t pack_lo_res(float a, float b) {
    float ra = a - __uint_as_float(__float_as_uint(a) & 0xFFFF0000u);
    float rb = b - __uint_as_float(__float_as_uint(b) & 0xFFFF0000u);
    uint32_t r;
    asm("cvt.rn.bf16x2.f32 %0, %1, %2;" : "=r"(r) : "f"(rb), "f"(ra));
    return r;
}
__device__ __forceinline__ void tsplit(float x, __nv_bfloat16* h, __nv_bfloat16* l) {
    uint32_t hb = __float_as_uint(x) & 0xFFFF0000u;
    __nv_bfloat16_raw raw; raw.x = (unsigned short)(hb >> 16);
    *h = __nv_bfloat16(raw);
    *l = __float2bfloat16(x - __uint_as_float(hb));
}

// ---------------------------------------------------------------------------
// fp32 -> (hi, lo) bf16 split (round-based), vectorized x4
// ---------------------------------------------------------------------------
__global__ void split_kernel(const float* __restrict__ src,
                             __nv_bfloat16* __restrict__ hi,
                             __nv_bfloat16* __restrict__ lo, int n4)
{
    int i = blockIdx.x * blockDim.x + threadIdx.x;
    if (i >= n4) return;
    float4 v = ((const float4*)src)[i];
    __nv_bfloat16 h0 = __float2bfloat16(v.x), h1 = __float2bfloat16(v.y);
    __nv_bfloat16 h2 = __float2bfloat16(v.z), h3 = __float2bfloat16(v.w);
    __nv_bfloat16 l0 = __float2bfloat16(v.x - __bfloat162float(h0));
    __nv_bfloat16 l1 = __float2bfloat16(v.y - __bfloat162float(h1));
    __nv_bfloat16 l2 = __float2bfloat16(v.z - __bfloat162float(h2));
    __nv_bfloat16 l3 = __float2bfloat16(v.w - __bfloat162float(h3));
    ((__nv_bfloat162*)hi)[2 * i]     = __halves2bfloat162(h0, h1);
    ((__nv_bfloat162*)hi)[2 * i + 1] = __halves2bfloat162(h2, h3);
    ((__nv_bfloat162*)lo)[2 * i]     = __halves2bfloat162(l0, l1);
    ((__nv_bfloat162*)lo)[2 * i + 1] = __halves2bfloat162(l2, l3);
}

// ---------------------------------------------------------------------------
// mma.sync split-bf16 GEMM (unchanged from R4, passing at rel 2e-5)
// ---------------------------------------------------------------------------
#define BK    32
#define TSTR  40
#define TILE_B (128 * TSTR * 2)
#define BUF_B  (4 * TILE_B)
#define GM_SMEM (2 * BUF_B)

template<int MODE>
__global__ void __launch_bounds__(256) gemm_mma(
    const __nv_bfloat16* __restrict__ Ah, const __nv_bfloat16* __restrict__ Al,
    const __nv_bfloat16* __restrict__ Wh, const __nv_bfloat16* __restrict__ Wl,
    const float* __restrict__ bias, float* __restrict__ C)
{
    extern __shared__ __align__(128) char smem[];
    const uint32_t sbase = smem_u32(smem);
    const int tid  = threadIdx.x;
    const int wid  = tid >> 5;
    const int lane = tid & 31;
    const int row0 = blockIdx.y * 128;
    const int col0 = blockIdx.x * 128;
    const int wm = (wid >> 2) * 64;
    const int wn = (wid & 3) * 32;

    const __nv_bfloat16* gsrc[4] = {Ah, Al, Wh, Wl};

    auto issue = [&](int kt, int buf) {
#pragma unroll
        for (int t = 0; t < 4; t++) {
            const __nv_bfloat16* g = gsrc[t];
            const int rb = (t < 2) ? row0 : col0;
            const uint32_t sb = sbase + buf * BUF_B + t * TILE_B;
#pragma unroll
            for (int i = 0; i < 2; i++) {
                const int ch = tid + i * 256;
                const int r = ch >> 2, c = ch & 3;
                cpa16(sb + r * (TSTR * 2) + c * 16,
                      g + (size_t)(rb + r) * DM + kt * BK + c * 8);
            }
        }
        cpa_commit();
    };

    float acc[4][4][4];
#pragma unroll
    for (int i = 0; i < 4; i++)
#pragma unroll
        for (int j = 0; j < 4; j++)
#pragma unroll
            for (int c = 0; c < 4; c++) acc[i][j][c] = 0.f;

    const int mi = lane >> 3;
    const int l7 = lane & 7;
    const int a_r  = ((mi & 1) << 3) + l7;
    const int a_kb = (mi >> 1) << 3;
    const int b_nt = mi >> 1;
    const int b_kb = (mi & 1) << 3;

    const int NKT = DM / BK;
    issue(0, 0);

    for (int kt = 0; kt < NKT; kt++) {
        const int buf = kt & 1;
        if (kt + 1 < NKT) { issue(kt + 1, buf ^ 1); cpa_wait<1>(); }
        else              { cpa_wait<0>(); }
        __syncthreads();

        const uint32_t sb = sbase + buf * BUF_B;
#pragma unroll
        for (int kh = 0; kh < 2; kh++) {
            uint32_t afh[4][4], afl[4][4];
#pragma unroll
            for (int mt = 0; mt < 4; mt++) {
                const uint32_t ad = sb +
                    (wm + mt * 16 + a_r) * (TSTR * 2) + (kh * 16 + a_kb) * 2;
                ldsm4(afh[mt], ad);
                ldsm4(afl[mt], ad + TILE_B);
            }
            uint32_t bfh[8], bfl[8];
#pragma unroll
            for (int g = 0; g < 2; g++) {
                const uint32_t bd = sb + 2 * TILE_B +
                    (wn + (2 * g + b_nt) * 8 + l7) * (TSTR * 2) +
                    (kh * 16 + b_kb) * 2;
                ldsm4(&bfh[g * 4], bd);
                ldsm4(&bfl[g * 4], bd + TILE_B);
            }
#pragma unroll
            for (int mt = 0; mt < 4; mt++)
#pragma unroll
                for (int nt = 0; nt < 4; nt++) {
                    float* c = acc[mt][nt];
                    mma16816(c, afh[mt], &bfh[nt * 2]);
                    mma16816(c, afh[mt], &bfl[nt * 2]);
                    mma16816(c, afl[mt], &bfh[nt * 2]);
                }
        }
        __syncthreads();
    }

#pragma unroll
    for (int mt = 0; mt < 4; mt++) {
#pragma unroll
        for (int nt = 0; nt < 4; nt++) {
            const int cc = col0 + wn + nt * 8 + (lane & 3) * 2;
            const float b0 = bias[cc], b1 = bias[cc + 1];
#pragma unroll
            for (int half = 0; half < 2; half++) {
                const int rr = row0 + wm + mt * 16 + (lane >> 2) + half * 8;
                float2 v;
                v.x = acc[mt][nt][half * 2 + 0] + b0;
                v.y = acc[mt][nt][half * 2 + 1] + b1;
                if (MODE == 0) {
                    *(float2*)(C + (size_t)rr * DM + cc) = v;
                } else {
                    const int b  = rr >> 11;
                    const int tt = rr & (SEQ - 1);
                    const int h  = cc >> 7;
                    const int d0 = cc & (DH - 1);
                    *(float2*)(C + (((size_t)(b * NH + h)) * SEQ + tt) * DH + d0) = v;
                }
            }
        }
    }
}

// ---------------------------------------------------------------------------
// RoPE + scale + truncation-split of q,k,v -> bf16 hi/lo arrays
// ---------------------------------------------------------------------------
__global__ void rope_split(const float* __restrict__ q, const float* __restrict__ k,
                           const float* __restrict__ v,
                           const float* __restrict__ sn, const float* __restrict__ cs,
                           __nv_bfloat16* __restrict__ qh, __nv_bfloat16* __restrict__ ql,
                           __nv_bfloat16* __restrict__ kh, __nv_bfloat16* __restrict__ kl,
                           __nv_bfloat16* __restrict__ vh, __nv_bfloat16* __restrict__ vl)
{
    const int idx = blockIdx.x * blockDim.x + threadIdx.x;   // BHN*SEQ*64
    const int d  = idx & 63;
    const int t  = (idx >> 6) & (SEQ - 1);
    const int bh = idx >> 17;
    const float s = sn[t * 64 + d];
    const float c = cs[t * 64 + d];
    const size_t base = ((size_t)bh * SEQ + t) * DH;
    const float scale = 0.08838834764831845f;   // 1/sqrt(128)

    float q1 = q[base + d], q2 = q[base + 64 + d];
    float rq1 = (q1 * c - q2 * s) * scale;
    float rq2 = (q1 * s + q2 * c) * scale;
    __nv_bfloat16 hh, ll;
    tsplit(rq1, &hh, &ll); qh[base + d] = hh;      ql[base + d] = ll;
    tsplit(rq2, &hh, &ll); qh[base + 64 + d] = hh; ql[base + 64 + d] = ll;

    float k1 = k[base + d], k2 = k[base + 64 + d];
    float rk1 = k1 * c - k2 * s;
    float rk2 = k1 * s + k2 * c;
    tsplit(rk1, &hh, &ll); kh[base + d] = hh;      kl[base + d] = ll;
    tsplit(rk2, &hh, &ll); kh[base + 64 + d] = hh; kl[base + 64 + d] = ll;

    float v1 = v[base + d], v2 = v[base + 64 + d];
    tsplit(v1, &hh, &ll); vh[base + d] = hh;       vl[base + d] = ll;
    tsplit(v2, &hh, &ll); vh[base + 64 + d] = hh;  vl[base + 64 + d] = ll;
}

// ---------------------------------------------------------------------------
// Tensor-core causal flash attention, split-bf16 for S=QK^T and O=PV.
// q-tile 128 rows, k-tile 64, 8 warps (16 q-rows each). Double-buffered K/V.
// ---------------------------------------------------------------------------
#define FSTR   272                     // smem row stride (bytes)
#define QT_B   (128 * FSTR)            // 34816
#define KT_B   (64 * FSTR)             // 17408
#define FBUF   (4 * KT_B)              // Kh,Kl,Vh,Vl = 69632
#define FL_SMEM (2 * QT_B + 2 * FBUF)  // 208896

__global__ void __launch_bounds__(256) flash_mma(
    const __nv_bfloat16* __restrict__ qh, const __nv_bfloat16* __restrict__ ql,
    const __nv_bfloat16* __restrict__ kh, const __nv_bfloat16* __restrict__ kl,
    const __nv_bfloat16* __restrict__ vh, const __nv_bfloat16* __restrict__ vl,
    __nv_bfloat16* __restrict__ att_hi, __nv_bfloat16* __restrict__ att_lo)
{
    extern __shared__ __align__(128) char smem[];
    const uint32_t sbase = smem_u32(smem);
    const int tid  = threadIdx.x;
    const int wid  = tid >> 5;
    const int lane = tid & 31;
    const int qt = (int)gridDim.x - 1 - (int)blockIdx.x;  // heavy tiles first
    const int bhid = blockIdx.y;
    const size_t hb = (size_t)bhid * SEQ * DH;

    const int mi_ = lane >> 3;
    const int l7  = lane & 7;
    const int a_r  = ((mi_ & 1) << 3) + l7;         // A-frag row
    const int a_kb = (mi_ >> 1) << 3;               // A-frag k offset
    const int b_nt = mi_ >> 1;                      // K B-frag n sub-tile
    const int b_kb = (mi_ & 1) << 3;                // K B-frag k offset

    // ---- load Q tile (hi+lo) ----
    {
        const __nv_bfloat16* src[2] = {qh, ql};
#pragma unroll
        for (int i = 0; i < 16; i++) {
            const int idx = tid + i * 256;
            const int t = idx >> 11, r = (idx >> 4) & 127, c = idx & 15;
            cpa16(sbase + t * QT_B + r * FSTR + c * 16,
                  src[t] + hb + (size_t)(qt * 128 + r) * DH + c * 8);
        }
        cpa_commit();
    }

    const __nv_bfloat16* kvsrc[4] = {kh, kl, vh, vl};
    auto issue_kv = [&](int j, int buf) {
        const uint32_t base = sbase + 2 * QT_B + buf * FBUF;
#pragma unroll
        for (int i = 0; i < 16; i++) {
            const int idx = tid + i * 256;
            const int s = idx >> 10, r = (idx >> 4) & 63, c = idx & 15;
            cpa16(base + s * KT_B + r * FSTR + c * 16,
                  kvsrc[s] + hb + (size_t)(j * 64 + r) * DH + c * 8);
        }
        cpa_commit();
    };

    float O[16][4];
#pragma unroll
    for (int nt = 0; nt < 16; nt++)
#pragma unroll
        for (int c = 0; c < 4; c++) O[nt][c] = 0.f;
    float mi0 = -INFINITY, mi1 = -INFINITY, li0 = 0.f, li1 = 0.f;

    const int rbase = qt * 128 + wid * 16;
    const int jmax = 2 * qt + 1;
    issue_kv(0, 0);

    for (int j = 0; j <= jmax; j++) {
        const int buf = j & 1;
        if (j < jmax) { issue_kv(j + 1, buf ^ 1); cpa_wait<1>(); }
        else          { cpa_wait<0>(); }
        __syncthreads();

        const bool active = (j * 64 <= rbase + 15);
        if (active) {
            const uint32_t kb = sbase + 2 * QT_B + buf * FBUF;

            // ---- S = Q K^T (split 3-term) ----
            float S[8][4];
#pragma unroll
            for (int nf = 0; nf < 8; nf++)
#pragma unroll
                for (int c = 0; c < 4; c++) S[nf][c] = 0.f;

#pragma unroll
            for (int k16 = 0; k16 < 8; k16++) {
                uint32_t aqh[4], aql[4];
                const uint32_t qa = sbase + (wid * 16 + a_r) * FSTR +
                                    (k16 * 16 + a_kb) * 2;
                ldsm4(aqh, qa);
                ldsm4(aql, qa + QT_B);
                uint32_t kfh[16], kfl[16];
#pragma unroll
                for (int g = 0; g < 4; g++) {
                    const uint32_t ka = kb + ((2 * g + b_nt) * 8 + l7) * FSTR +
                                        (k16 * 16 + b_kb) * 2;
                    ldsm4(&kfh[g * 4], ka);
                    ldsm4(&kfl[g * 4], ka + KT_B);
                }
#pragma unroll
                for (int nf = 0; nf < 8; nf++) {
                    const uint32_t* Bh = &kfh[nf * 2];
                    const uint32_t* Bl = &kfl[nf * 2];
                    mma16816(S[nf], aqh, Bh);
                    mma16816(S[nf], aqh, Bl);
                    mma16816(S[nf], aql, Bh);
                }
            }

            // ---- causal mask ----
            if (j * 64 + 63 > rbase) {
                const int r0 = rbase + (lane >> 2), r1 = r0 + 8;
#pragma unroll
                for (int nf = 0; nf < 8; nf++) {
                    const int c0 = j * 64 + nf * 8 + (lane & 3) * 2;
                    if (c0 > r0)     S[nf][0] = -1e30f;
                    if (c0 + 1 > r0) S[nf][1] = -1e30f;
                    if (c0 > r1)     S[nf][2] = -1e30f;
                    if (c0 + 1 > r1) S[nf][3] = -1e30f;
                }
            }

            // ---- online softmax (rows lane/4 and lane/4+8) ----
            float rx0 = -1e30f, rx1 = -1e30f;
#pragma unroll
            for (int nf = 0; nf < 8; nf++) {
                rx0 = fmaxf(rx0, fmaxf(S[nf][0], S[nf][1]));
                rx1 = fmaxf(rx1, fmaxf(S[nf][2], S[nf][3]));
            }
            rx0 = fmaxf(rx0, __shfl_xor_sync(0xffffffffu, rx0, 1));
            rx0 = fmaxf(rx0, __shfl_xor_sync(0xffffffffu, rx0, 2));
            rx1 = fmaxf(rx1, __shfl_xor_sync(0xffffffffu, rx1, 1));
            rx1 = fmaxf(rx1, __shfl_xor_sync(0xffffffffu, rx1, 2));
            const float mn0 = fmaxf(mi0, rx0), mn1 = fmaxf(mi1, rx1);
            const float al0 = __expf(mi0 - mn0), al1 = __expf(mi1 - mn1);
            float s0 = 0.f, s1 = 0.f;
#pragma unroll
            for (int nf = 0; nf < 8; nf++) {
                S[nf][0] = __expf(S[nf][0] - mn0);
                S[nf][1] = __expf(S[nf][1] - mn0);
                S[nf][2] = __expf(S[nf][2] - mn1);
                S[nf][3] = __expf(S[nf][3] - mn1);
                s0 += S[nf][0] + S[nf][1];
                s1 += S[nf][2] + S[nf][3];
            }
            s0 += __shfl_xor_sync(0xffffffffu, s0, 1);
            s0 += __shfl_xor_sync(0xffffffffu, s0, 2);
            s1 += __shfl_xor_sync(0xffffffffu, s1, 1);
            s1 += __shfl_xor_sync(0xffffffffu, s1, 2);
            li0 = li0 * al0 + s0; mi0 = mn0;
            li1 = li1 * al1 + s1; mi1 = mn1;
#pragma unroll
            for (int nt = 0; nt < 16; nt++) {
                O[nt][0] *= al0; O[nt][1] *= al0;
                O[nt][2] *= al1; O[nt][3] *= al1;
            }

            // ---- pack P to A-fragments (truncation split) ----
            uint32_t Ph[4][4], Pl[4][4];
#pragma unroll
            for (int kc = 0; kc < 4; kc++) {
                Ph[kc][0] = pack_hi_trunc(S[2*kc][0],   S[2*kc][1]);
                Ph[kc][1] = pack_hi_trunc(S[2*kc][2],   S[2*kc][3]);
                Ph[kc][2] = pack_hi_trunc(S[2*kc+1][0], S[2*kc+1][1]);
                Ph[kc][3] = pack_hi_trunc(S[2*kc+1][2], S[2*kc+1][3]);
                Pl[kc][0] = pack_lo_res(S[2*kc][0],   S[2*kc][1]);
                Pl[kc][1] = pack_lo_res(S[2*kc][2],   S[2*kc][3]);
                Pl[kc][2] = pack_lo_res(S[2*kc+1][0], S[2*kc+1][1]);
                Pl[kc][3] = pack_lo_res(S[2*kc+1][2], S[2*kc+1][3]);
            }

            // ---- O += P V (split 3-term), V via ldmatrix.trans ----
            const uint32_t vb = kb + 2 * KT_B;
#pragma unroll
            for (int kc = 0; kc < 4; kc++) {
#pragma unroll
                for (int half = 0; half < 2; half++) {
                    uint32_t vfh[16], vfl[16];
#pragma unroll
                    for (int g = 0; g < 4; g++) {
                        const int gg = half * 4 + g;
                        const uint32_t va = vb +
                            (kc * 16 + ((mi_ & 1) << 3) + l7) * FSTR +
                            (gg * 16 + ((mi_ >> 1) << 3)) * 2;
                        ldsm4t(&vfh[g * 4], va);
                        ldsm4t(&vfl[g * 4], va + KT_B);
                    }
#pragma unroll
                    for (int nf = 0; nf < 8; nf++) {
                        const int nt = half * 8 + nf;
                        const uint32_t* Bh = &vfh[nf * 2];
                        const uint32_t* Bl = &vfl[nf * 2];
                        mma16816(O[nt], Ph[kc], Bh);
                        mma16816(O[nt], Ph[kc], Bl);
                        mma16816(O[nt], Pl[kc], Bh);
                    }
                }
            }
        }
        __syncthreads();
    }

    // ---- epilogue: normalize, truncation-split, store to (B,T,D) ----
    const float inv0 = 1.f / li0, inv1 = 1.f / li1;
    const int b = bhid >> 4, h = bhid & 15;
    const int t0 = rbase + (lane >> 2), t1 = t0 + 8;
#pragma unroll
    for (int nt = 0; nt < 16; nt++) {
        const int col = h * DH + nt * 8 + (lane & 3) * 2;
        const size_t o0 = ((size_t)(b * SEQ) + t0) * DM + col;
        const size_t o1 = ((size_t)(b * SEQ) + t1) * DM + col;
        const float x0 = O[nt][0] * inv0, x1 = O[nt][1] * inv0;
        const float y0 = O[nt][2] * inv1, y1 = O[nt][3] * inv1;
        *(uint32_t*)(att_hi + o0) = pack_hi_trunc(x0, x1);
        *(uint32_t*)(att_lo + o0) = pack_lo_res(x0, x1);
        *(uint32_t*)(att_hi + o1) = pack_hi_trunc(y0, y1);
        *(uint32_t*)(att_lo + o1) = pack_lo_res(y0, y1);
    }
}

// ---------------------------------------------------------------------------
extern "C" void kernel_launch(void* const* d_in, const int* in_sizes, int n_in,
                              void* d_out, int out_size)
{
    (void)in_sizes; (void)n_in; (void)out_size;
    const float* x  = (const float*)d_in[0];
    const float* Wq = (const float*)d_in[1];
    const float* bq = (const float*)d_in[2];
    const float* Wk = (const float*)d_in[3];
    const float* bk = (const float*)d_in[4];
    const float* Wv = (const float*)d_in[5];
    const float* bv = (const float*)d_in[6];
    const float* Wo = (const float*)d_in[7];
    const float* bo = (const float*)d_in[8];
    const float* sn = (const float*)d_in[9];
    const float* cs = (const float*)d_in[10];
    float* out = (float*)d_out;

    float *q, *k, *v;
    __nv_bfloat16 *xh, *xl, *wh, *wl, *ah, *al;
    __nv_bfloat16 *qh, *ql, *kh, *kl, *vh, *vl;
    cudaGetSymbolAddress((void**)&q,  g_q);
    cudaGetSymbolAddress((void**)&k,  g_k);
    cudaGetSymbolAddress((void**)&v,  g_v);
    cudaGetSymbolAddress((void**)&xh, g_xh);
    cudaGetSymbolAddress((void**)&xl, g_xl);
    cudaGetSymbolAddress((void**)&wh, g_wh);
    cudaGetSymbolAddress((void**)&wl, g_wl);
    cudaGetSymbolAddress((void**)&ah, g_ah);
    cudaGetSymbolAddress((void**)&al, g_al);
    cudaGetSymbolAddress((void**)&qh, g_qh);
    cudaGetSymbolAddress((void**)&ql, g_ql);
    cudaGetSymbolAddress((void**)&kh, g_kh);
    cudaGetSymbolAddress((void**)&kl, g_kl);
    cudaGetSymbolAddress((void**)&vh, g_vh);
    cudaGetSymbolAddress((void**)&vl, g_vl);

    cudaFuncSetAttribute(gemm_mma<0>, cudaFuncAttributeMaxDynamicSharedMemorySize, GM_SMEM);
    cudaFuncSetAttribute(gemm_mma<1>, cudaFuncAttributeMaxDynamicSharedMemorySize, GM_SMEM);
    cudaFuncSetAttribute(flash_mma, cudaFuncAttributeMaxDynamicSharedMemorySize, FL_SMEM);

    // split conversions
    split_kernel<<<(MROWS * DM / 4) / 256, 256>>>(x, xh, xl, MROWS * DM / 4);
    const int wn4 = DM * DM / 4;
    split_kernel<<<wn4 / 256, 256>>>(Wq, wh + 0 * DM * DM, wl + 0 * DM * DM, wn4);
    split_kernel<<<wn4 / 256, 256>>>(Wk, wh + 1 * DM * DM, wl + 1 * DM * DM, wn4);
    split_kernel<<<wn4 / 256, 256>>>(Wv, wh + 2 * DM * DM, wl + 2 * DM * DM, wn4);
    split_kernel<<<wn4 / 256, 256>>>(Wo, wh + 3 * DM * DM, wl + 3 * DM * DM, wn4);

    // QKV projections on tensor cores (scatter into (B,H,T,Dh))
    const dim3 ggrid(DM / 128, MROWS / 128);   // (16, 32)
    gemm_mma<1><<<ggrid, 256, GM_SMEM>>>(xh, xl, wh + 0 * DM * DM, wl + 0 * DM * DM, bq, q);
    gemm_mma<1><<<ggrid, 256, GM_SMEM>>>(xh, xl, wh + 1 * DM * DM, wl + 1 * DM * DM, bk, k);
    gemm_mma<1><<<ggrid, 256, GM_SMEM>>>(xh, xl, wh + 2 * DM * DM, wl + 2 * DM * DM, bv, v);

    // RoPE + scale + split to bf16 hi/lo
    rope_split<<<(BHN * SEQ * 64) / 256, 256>>>(q, k, v, sn, cs, qh, ql, kh, kl, vh, vl);

    // Tensor-core flash attention (emits split-bf16 att)
    flash_mma<<<dim3(SEQ / 128, BHN), 256, FL_SMEM>>>(qh, ql, kh, kl, vh, vl, ah, al);

    // Output projection on tensor cores
    gemm_mma<0><<<ggrid, 256, GM_SMEM>>>(ah, al, wh + 3 * DM * DM, wl + 3 * DM * DM, bo, out);
}